// round 6
// baseline (speedup 1.0000x reference)
#include <cuda_runtime.h>
#include <math.h>
#include <stdint.h>

#define NF 26
#define ND 16
#define H1 256
#define H2 128
#define ROWS 128
#define K1 (NF*ND)     // 416
#define EPSF 1e-5f
#define H1S 136        // h1 smem stride (floats)
#define NT 512

// smem float offsets
#define OFF_A      0
#define OFF_FM     (K1*ROWS)          // 53248
#define OFF_LOGIT  (OFF_FM + 128)
#define OFF_S1     (OFF_LOGIT + 128)
#define OFF_B1     (OFF_S1 + 256)
#define OFF_S2     (OFF_B1 + 256)
#define OFF_B2     (OFF_S2 + 128)
#define OFF_W3     (OFF_B2 + 128)
#define SMEM_FLOATS (OFF_W3 + 128)    // 54400 -> 217600 B

__device__ __forceinline__ uint32_t smem_u32(const void* p){
    uint32_t a;
    asm("{ .reg .u64 t; cvta.to.shared.u64 t, %1; cvt.u32.u64 %0, t; }" : "=r"(a) : "l"(p));
    return a;
}
__device__ __forceinline__ unsigned long long packf2(float x){
    unsigned long long r;
    asm("mov.b64 %0, {%1, %1};" : "=l"(r) : "f"(x));
    return r;
}
__device__ __forceinline__ unsigned long long pack2(float lo, float hi){
    unsigned long long r;
    asm("mov.b64 %0, {%1, %2};" : "=l"(r) : "f"(lo), "f"(hi));
    return r;
}
__device__ __forceinline__ void unpack2(unsigned long long a, float& lo, float& hi){
    asm("mov.b64 {%0, %1}, %2;" : "=f"(lo), "=f"(hi) : "l"(a));
}
__device__ __forceinline__ void fma2(unsigned long long& a, unsigned long long e, unsigned long long w){
    asm("fma.rn.f32x2 %0, %1, %2, %0;" : "+l"(a) : "l"(e), "l"(w));
}
__device__ __forceinline__ void lds2x64(unsigned long long& a, unsigned long long& b, uint32_t addr){
    asm volatile("ld.shared.v2.u64 {%0, %1}, [%2];" : "=l"(a), "=l"(b) : "r"(addr));
}
__device__ __forceinline__ void sts64(uint32_t addr, unsigned long long v){
    asm volatile("st.shared.u64 [%0], %1;" :: "r"(addr), "l"(v));
}

__global__ __launch_bounds__(NT, 1)
void deepfm_v4(const int* __restrict__ X, const float* __restrict__ emb1,
               const float* __restrict__ emb2,
               const float* __restrict__ W1, const float* __restrict__ b1,
               const float* __restrict__ g1, const float* __restrict__ be1,
               const float* __restrict__ m1, const float* __restrict__ v1,
               const float* __restrict__ W2, const float* __restrict__ b2,
               const float* __restrict__ g2, const float* __restrict__ be2,
               const float* __restrict__ m2, const float* __restrict__ v2,
               const float* __restrict__ W3, const float* __restrict__ b3,
               float* __restrict__ out, int Btot, int V)
{
    extern __shared__ float sm[];
    float* e2sT    = sm + OFF_A;      // [416][128], reused later as h1s [256][136]
    float* fm_s    = sm + OFF_FM;
    float* logit_s = sm + OFF_LOGIT;
    float* S1f     = sm + OFF_S1;
    float* B1f     = sm + OFF_B1;
    float* S2f     = sm + OFF_S2;
    float* B2f     = sm + OFF_B2;
    float* W3s     = sm + OFF_W3;

    const int tid = threadIdx.x;
    const int b0  = blockIdx.x * ROWS;
    const uint32_t smbase = smem_u32(sm);

    if (tid < 128) { fm_s[tid] = 0.f; logit_s[tid] = 0.f; }
    if (tid < 256) {
        float s = g1[tid] * rsqrtf(v1[tid] + EPSF);
        S1f[tid] = s; B1f[tid] = be1[tid] + (b1[tid] - m1[tid]) * s;
        if (tid < 128) {
            float s2 = g2[tid] * rsqrtf(v2[tid] + EPSF);
            S2f[tid] = s2; B2f[tid] = be2[tid] + (b2[tid] - m2[tid]) * s2;
            W3s[tid] = W3[tid];
        }
    }
    __syncthreads();

    // ---- Phase 1: gather e2 transposed [k][row] + first-order FM ----
    for (int p = tid; p < ROWS*NF; p += NT) {
        int r = p & (ROWS-1);
        int f = p >> 7;                 // 0..25
        int idx = X[(size_t)(b0 + r) * NF + f];
        atomicAdd(&fm_s[r], emb1[(size_t)f * V + idx]);
        const float4* src = (const float4*)(emb2 + ((size_t)f * V + idx) * ND);
        #pragma unroll
        for (int q = 0; q < 4; q++) {
            float4 v = src[q];
            e2sT[(f*ND + 4*q + 0)*ROWS + r] = v.x;
            e2sT[(f*ND + 4*q + 1)*ROWS + r] = v.y;
            e2sT[(f*ND + 4*q + 2)*ROWS + r] = v.z;
            e2sT[(f*ND + 4*q + 3)*ROWS + r] = v.w;
        }
    }
    __syncthreads();

    // ---- Phase 2: second-order FM ----
    for (int p = tid; p < ROWS*ND; p += NT) {
        int r = p & (ROWS-1);
        int d = p >> 7;                 // 0..15
        float s = 0.f, sq = 0.f;
        #pragma unroll
        for (int f = 0; f < NF; f++) {
            float v = e2sT[(f*ND + d)*ROWS + r];
            s += v; sq += v*v;
        }
        atomicAdd(&fm_s[r], 0.5f*(s*s - sq));
    }

    // ---- Phase 3: GEMM1 (K=416 -> 256 cols), thread = 8 cols x 8 rows ----
    const int jq = tid >> 4;            // 0..31 -> cols 8jq..8jq+7
    const int rg = tid & 15;            // 0..15 -> rows 8rg..8rg+7
    unsigned long long acc[32];         // [c][p]: c<8 cols, p<4 row-pairs
    #pragma unroll
    for (int i = 0; i < 32; i++) acc[i] = 0ull;
    {
        const float4* wp = (const float4*)(W1 + 8*jq);   // 2 float4 per k
        uint32_t ea = smbase + (uint32_t)rg * 32u;       // + k*512 per k
        #pragma unroll 2
        for (int k = 0; k < K1; k++) {
            float4 wa = wp[(size_t)k * (H1/4)];
            float4 wb = wp[(size_t)k * (H1/4) + 1];
            unsigned long long e[4];
            lds2x64(e[0], e[1], ea);
            lds2x64(e[2], e[3], ea + 16u);
            ea += 512u;
            unsigned long long w[8];
            w[0]=packf2(wa.x); w[1]=packf2(wa.y); w[2]=packf2(wa.z); w[3]=packf2(wa.w);
            w[4]=packf2(wb.x); w[5]=packf2(wb.y); w[6]=packf2(wb.z); w[7]=packf2(wb.w);
            #pragma unroll
            for (int c = 0; c < 8; c++)
                #pragma unroll
                for (int p = 0; p < 4; p++)
                    fma2(acc[c*4+p], e[p], w[c]);
        }
    }
    __syncthreads();    // all e2sT reads done before overwrite

    // ---- BN1 + ReLU -> h1s [256][136] ----
    {
        #pragma unroll
        for (int c = 0; c < 8; c++) {
            int col = 8*jq + c;
            float S = S1f[col], Bv = B1f[col];
            uint32_t ha = smbase + ((uint32_t)col * H1S + (uint32_t)rg * 8u) * 4u;
            #pragma unroll
            for (int p = 0; p < 4; p++) {
                float lo, hi; unpack2(acc[c*4+p], lo, hi);
                lo = fmaxf(lo*S + Bv, 0.f);
                hi = fmaxf(hi*S + Bv, 0.f);
                sts64(ha + (uint32_t)p * 8u, pack2(lo, hi));
            }
        }
    }
    __syncthreads();

    // ---- Phase 4: GEMM2 (K=256 -> 128 cols), thread = 4 cols x 8 rows ----
    const int jq2 = tid >> 4;           // 0..31 -> cols 4jq2..4jq2+3
    const int rg2 = tid & 15;           // 0..15 -> rows 8rg2..8rg2+7
    unsigned long long acc2[16];        // [c][p]: c<4, p<4
    #pragma unroll
    for (int i = 0; i < 16; i++) acc2[i] = 0ull;
    {
        const float4* wp2 = (const float4*)(W2 + 4*jq2);
        uint32_t ha = smbase + (uint32_t)rg2 * 32u;      // + k*544 per k
        #pragma unroll 2
        for (int k = 0; k < H1; k++) {
            float4 wv = wp2[(size_t)k * (H2/4)];
            unsigned long long e[4];
            lds2x64(e[0], e[1], ha);
            lds2x64(e[2], e[3], ha + 16u);
            ha += (uint32_t)(H1S * 4);
            unsigned long long w0 = packf2(wv.x), w1 = packf2(wv.y),
                               w2 = packf2(wv.z), w3p = packf2(wv.w);
            #pragma unroll
            for (int p = 0; p < 4; p++) {
                fma2(acc2[0*4+p], e[p], w0);
                fma2(acc2[1*4+p], e[p], w1);
                fma2(acc2[2*4+p], e[p], w2);
                fma2(acc2[3*4+p], e[p], w3p);
            }
        }
    }

    // ---- BN2 + ReLU + W3 partial dots -> smem logits ----
    {
        float contrib[8] = {0,0,0,0,0,0,0,0};
        #pragma unroll
        for (int c = 0; c < 4; c++) {
            int col = 4*jq2 + c;
            float S = S2f[col], Bv = B2f[col], w3 = W3s[col];
            #pragma unroll
            for (int p = 0; p < 4; p++) {
                float lo, hi; unpack2(acc2[c*4+p], lo, hi);
                contrib[2*p]   += fmaxf(lo*S + Bv, 0.f) * w3;
                contrib[2*p+1] += fmaxf(hi*S + Bv, 0.f) * w3;
            }
        }
        #pragma unroll
        for (int rr = 0; rr < 8; rr++)
            atomicAdd(&logit_s[8*rg2 + rr], contrib[rr]);
    }
    __syncthreads();

    // ---- Epilogue ----
    if (tid < ROWS) {
        float x = logit_s[tid] + fm_s[tid] + b3[0];
        out[b0 + tid] = 1.f / (1.f + expf(-x));
    }
}

extern "C" void kernel_launch(void* const* d_in, const int* in_sizes, int n_in,
                              void* d_out, int out_size)
{
    const int*   X    = (const int*)  d_in[0];
    const float* emb1 = (const float*)d_in[1];
    const float* emb2 = (const float*)d_in[2];
    const float* W1   = (const float*)d_in[3];
    const float* b1   = (const float*)d_in[4];
    const float* g1   = (const float*)d_in[5];
    const float* be1  = (const float*)d_in[6];
    const float* m1   = (const float*)d_in[7];
    const float* v1   = (const float*)d_in[8];
    const float* W2   = (const float*)d_in[9];
    const float* b2   = (const float*)d_in[10];
    const float* g2   = (const float*)d_in[11];
    const float* be2  = (const float*)d_in[12];
    const float* m2   = (const float*)d_in[13];
    const float* v2   = (const float*)d_in[14];
    const float* W3   = (const float*)d_in[15];
    const float* b3   = (const float*)d_in[16];
    float* out = (float*)d_out;

    int B = in_sizes[0] / NF;
    int V = in_sizes[1] / NF;

    int smem = SMEM_FLOATS * (int)sizeof(float);   // 217600 B
    cudaFuncSetAttribute(deepfm_v4, cudaFuncAttributeMaxDynamicSharedMemorySize, smem);
    deepfm_v4<<<B/ROWS, NT, smem>>>(X, emb1, emb2, W1, b1, g1, be1, m1, v1,
                                    W2, b2, g2, be2, m2, v2, W3, b3,
                                    out, B, V);
}

// round 8
// speedup vs baseline: 1.1480x; 1.1480x over previous
#include <cuda_runtime.h>
#include <math.h>
#include <stdint.h>

#define NF 26
#define ND 16
#define H1 256
#define H2 128
#define ROWS 64
#define K1 (NF*ND)     // 416
#define EPSF 1e-5f
#define NT 512
#define KC1 32
#define NCH1 13        // 13*32 = 416
#define KC2 64
#define NCH2 4         // 4*64 = 256

// float offsets in dynamic smem
#define OFF_A     0            // A [416][64] = 26624 fl; later h1s [256][64] = 16384 fl
#define OFF_WB0   26624        // 8192 fl (32KB)
#define OFF_WB1   34816        // 8192 fl
#define OFF_FM    43008
#define OFF_LOGIT (OFF_FM + 64)
#define OFF_S1    (OFF_LOGIT + 64)
#define OFF_B1    (OFF_S1 + 256)
#define OFF_S2    (OFF_B1 + 256)
#define OFF_B2    (OFF_S2 + 128)
#define OFF_W3    (OFF_B2 + 128)
#define SMEM_FLOATS (OFF_W3 + 128)   // 44032 -> 176128 B

__device__ __forceinline__ uint32_t smem_u32(const void* p){
    uint32_t a;
    asm("{ .reg .u64 t; cvta.to.shared.u64 t, %1; cvt.u32.u64 %0, t; }" : "=r"(a) : "l"(p));
    return a;
}
__device__ __forceinline__ unsigned long long packf2(float x){
    unsigned long long r;
    asm("mov.b64 %0, {%1, %1};" : "=l"(r) : "f"(x));
    return r;
}
__device__ __forceinline__ void unpack2(unsigned long long a, float& lo, float& hi){
    asm("mov.b64 {%0, %1}, %2;" : "=f"(lo), "=f"(hi) : "l"(a));
}
__device__ __forceinline__ void fma2(unsigned long long& a, unsigned long long e, unsigned long long w){
    asm("fma.rn.f32x2 %0, %1, %2, %0;" : "+l"(a) : "l"(e), "l"(w));
}
__device__ __forceinline__ void lds4f(float& a, float& b, float& c, float& d, uint32_t addr){
    asm volatile("ld.shared.v4.f32 {%0,%1,%2,%3}, [%4];"
                 : "=f"(a), "=f"(b), "=f"(c), "=f"(d) : "r"(addr));
}
__device__ __forceinline__ void lds2u64(unsigned long long& a, unsigned long long& b, uint32_t addr){
    asm volatile("ld.shared.v2.u64 {%0, %1}, [%2];" : "=l"(a), "=l"(b) : "r"(addr));
}
__device__ __forceinline__ void sts4f(uint32_t addr, float a, float b, float c, float d){
    asm volatile("st.shared.v4.f32 [%0], {%1,%2,%3,%4};"
                 :: "r"(addr), "f"(a), "f"(b), "f"(c), "f"(d));
}

__global__ __launch_bounds__(NT, 1)
void deepfm_v6(const int* __restrict__ X, const float* __restrict__ emb1,
               const float* __restrict__ emb2,
               const float* __restrict__ W1, const float* __restrict__ b1,
               const float* __restrict__ g1, const float* __restrict__ be1,
               const float* __restrict__ m1, const float* __restrict__ v1,
               const float* __restrict__ W2, const float* __restrict__ b2,
               const float* __restrict__ g2, const float* __restrict__ be2,
               const float* __restrict__ m2, const float* __restrict__ v2,
               const float* __restrict__ W3, const float* __restrict__ b3,
               float* __restrict__ out, int Btot, int V)
{
    extern __shared__ float sm[];
    float* As      = sm + OFF_A;       // [416][64]; later h1s [256][64]
    float* fm_s    = sm + OFF_FM;
    float* logit_s = sm + OFF_LOGIT;
    float* S1f     = sm + OFF_S1;
    float* B1f     = sm + OFF_B1;
    float* S2f     = sm + OFF_S2;
    float* B2f     = sm + OFF_B2;
    float* W3s     = sm + OFF_W3;

    const int tid = threadIdx.x;
    const int b0  = blockIdx.x * ROWS;
    const uint32_t smbase = smem_u32(sm);

    if (tid < 64) { fm_s[tid] = 0.f; logit_s[tid] = 0.f; }
    if (tid < 256) {
        float s = g1[tid] * rsqrtf(v1[tid] + EPSF);
        S1f[tid] = s; B1f[tid] = be1[tid] + (b1[tid] - m1[tid]) * s;
        if (tid < 128) {
            float s2 = g2[tid] * rsqrtf(v2[tid] + EPSF);
            S2f[tid] = s2; B2f[tid] = be2[tid] + (b2[tid] - m2[tid]) * s2;
            W3s[tid] = W3[tid];
        }
    }
    __syncthreads();

    // ---- Phase 1: gather e2 transposed [k][row] + first-order FM ----
    for (int p = tid; p < ROWS*NF; p += NT) {
        int r = p & (ROWS-1);
        int f = p >> 6;                 // 0..25
        int idx = X[(size_t)(b0 + r) * NF + f];
        atomicAdd(&fm_s[r], emb1[(size_t)f * V + idx]);
        const float4* src = (const float4*)(emb2 + ((size_t)f * V + idx) * ND);
        #pragma unroll
        for (int q = 0; q < 4; q++) {
            float4 v = src[q];
            As[(f*ND + 4*q + 0)*ROWS + r] = v.x;
            As[(f*ND + 4*q + 1)*ROWS + r] = v.y;
            As[(f*ND + 4*q + 2)*ROWS + r] = v.z;
            As[(f*ND + 4*q + 3)*ROWS + r] = v.w;
        }
    }
    __syncthreads();

    const float4* W1g = (const float4*)W1;   // [416][64 float4]
    const float4* W2g = (const float4*)W2;   // [256][32 float4]
    float4* WB0 = (float4*)(sm + OFF_WB0);
    float4* WB1 = (float4*)(sm + OFF_WB1);

    // ---- prefetch W1 chunk 0 while FM2 computes ----
    float4 pf[4];
    {
        #pragma unroll
        for (int i = 0; i < 4; i++) {
            int t = tid + i * NT;                // < 2048
            pf[i] = W1g[(size_t)(t >> 6) * 64 + (t & 63)];
        }
    }
    // ---- Phase 2: second-order FM ----
    for (int p = tid; p < ROWS*ND; p += NT) {
        int r = p & (ROWS-1);
        int d = p >> 6;                 // 0..15
        float s = 0.f, sq = 0.f;
        #pragma unroll
        for (int f = 0; f < NF; f++) {
            float v = As[(f*ND + d)*ROWS + r];
            s += v; sq += v*v;
        }
        atomicAdd(&fm_s[r], 0.5f*(s*s - sq));
    }
    {
        #pragma unroll
        for (int i = 0; i < 4; i++) {
            int t = tid + i * NT;
            WB0[(t >> 6) * 64 + (t & 63)] = pf[i];
        }
    }
    __syncthreads();

    // ---- GEMM1: K=416 (13 chunks of 32), thread = 8 cols x 4 rows ----
    const int jq = tid >> 4;            // 0..31 -> cols 8jq..8jq+7 (4 col-pairs)
    const int rg = tid & 15;            // rows 4rg..4rg+3
    unsigned long long acc[16];         // [p][cp]: p<4 rows, cp<4 colpairs
    #pragma unroll
    for (int i = 0; i < 16; i++) acc[i] = 0ull;
    {
        const uint32_t ebase = smbase + (uint32_t)OFF_A*4u + (uint32_t)rg*16u;
        #pragma unroll 1
        for (int c = 0; c < NCH1; c++) {
            if (c + 1 < NCH1) {
                #pragma unroll
                for (int i = 0; i < 4; i++) {
                    int t = tid + i * NT;
                    pf[i] = W1g[(size_t)((c+1)*KC1 + (t >> 6)) * 64 + (t & 63)];
                }
            }
            uint32_t ea = ebase + (uint32_t)(c * KC1) * 256u;
            uint32_t wa = smbase + (uint32_t)((c & 1) ? OFF_WB1 : OFF_WB0)*4u + (uint32_t)jq*32u;
            #pragma unroll 8
            for (int kk = 0; kk < KC1; kk++) {
                float e0, e1, e2, e3;
                lds4f(e0, e1, e2, e3, ea);
                ea += 256u;
                unsigned long long w0, w1, w2, w3p;
                lds2u64(w0, w1, wa);
                lds2u64(w2, w3p, wa + 16u);
                wa += 1024u;
                unsigned long long E0 = packf2(e0), E1 = packf2(e1),
                                   E2 = packf2(e2), E3 = packf2(e3);
                fma2(acc[0],  E0, w0); fma2(acc[1],  E0, w1); fma2(acc[2],  E0, w2); fma2(acc[3],  E0, w3p);
                fma2(acc[4],  E1, w0); fma2(acc[5],  E1, w1); fma2(acc[6],  E1, w2); fma2(acc[7],  E1, w3p);
                fma2(acc[8],  E2, w0); fma2(acc[9],  E2, w1); fma2(acc[10], E2, w2); fma2(acc[11], E2, w3p);
                fma2(acc[12], E3, w0); fma2(acc[13], E3, w1); fma2(acc[14], E3, w2); fma2(acc[15], E3, w3p);
            }
            if (c + 1 < NCH1) {
                float4* dst = (c & 1) ? WB0 : WB1;
                #pragma unroll
                for (int i = 0; i < 4; i++) {
                    int t = tid + i * NT;
                    dst[(t >> 6) * 64 + (t & 63)] = pf[i];
                }
            }
            __syncthreads();
        }
    }

    // ---- BN1 + ReLU -> h1s [256][64] (reuses A region) + prefetch W2 chunk 0 ----
    {
        #pragma unroll
        for (int i = 0; i < 4; i++) {
            int t = tid + i * NT;               // < 2048
            pf[i] = W2g[(size_t)(t >> 5) * 32 + (t & 31)];
        }
        #pragma unroll
        for (int cp = 0; cp < 4; cp++) {
            int c0 = 8*jq + 2*cp;
            float Sa = S1f[c0],   Ba = B1f[c0];
            float Sb = S1f[c0+1], Bb = B1f[c0+1];
            float lo0,hi0, lo1,hi1, lo2,hi2, lo3,hi3;
            unpack2(acc[0*4+cp], lo0, hi0);
            unpack2(acc[1*4+cp], lo1, hi1);
            unpack2(acc[2*4+cp], lo2, hi2);
            unpack2(acc[3*4+cp], lo3, hi3);
            uint32_t da = smbase + (uint32_t)OFF_A*4u + (uint32_t)c0 * 256u + (uint32_t)rg*16u;
            sts4f(da,
                  fmaxf(lo0*Sa + Ba, 0.f), fmaxf(lo1*Sa + Ba, 0.f),
                  fmaxf(lo2*Sa + Ba, 0.f), fmaxf(lo3*Sa + Ba, 0.f));
            sts4f(da + 256u,
                  fmaxf(hi0*Sb + Bb, 0.f), fmaxf(hi1*Sb + Bb, 0.f),
                  fmaxf(hi2*Sb + Bb, 0.f), fmaxf(hi3*Sb + Bb, 0.f));
        }
        #pragma unroll
        for (int i = 0; i < 4; i++) {
            int t = tid + i * NT;
            WB0[(t >> 5) * 32 + (t & 31)] = pf[i];
        }
    }
    __syncthreads();

    // ---- GEMM2: K=256 (4 chunks of 64), thread = 4 cols x 4 rows ----
    const int jq2 = tid >> 4;           // 0..31 -> cols 4jq2..4jq2+3 (2 col-pairs)
    const int rg2 = tid & 15;           // rows 4rg2..4rg2+3
    unsigned long long acc2[8];
    #pragma unroll
    for (int i = 0; i < 8; i++) acc2[i] = 0ull;
    {
        const uint32_t ebase = smbase + (uint32_t)OFF_A*4u + (uint32_t)rg2*16u;
        #pragma unroll 1
        for (int c = 0; c < NCH2; c++) {
            if (c + 1 < NCH2) {
                #pragma unroll
                for (int i = 0; i < 4; i++) {
                    int t = tid + i * NT;
                    pf[i] = W2g[(size_t)((c+1)*KC2 + (t >> 5)) * 32 + (t & 31)];
                }
            }
            uint32_t ea = ebase + (uint32_t)(c * KC2) * 256u;
            uint32_t wa = smbase + (uint32_t)((c & 1) ? OFF_WB1 : OFF_WB0)*4u + (uint32_t)jq2*16u;
            #pragma unroll 8
            for (int kk = 0; kk < KC2; kk++) {
                float e0, e1, e2, e3;
                lds4f(e0, e1, e2, e3, ea);
                ea += 256u;
                unsigned long long w0, w1;
                lds2u64(w0, w1, wa);
                wa += 512u;
                unsigned long long E0 = packf2(e0), E1 = packf2(e1),
                                   E2 = packf2(e2), E3 = packf2(e3);
                fma2(acc2[0], E0, w0); fma2(acc2[1], E0, w1);
                fma2(acc2[2], E1, w0); fma2(acc2[3], E1, w1);
                fma2(acc2[4], E2, w0); fma2(acc2[5], E2, w1);
                fma2(acc2[6], E3, w0); fma2(acc2[7], E3, w1);
            }
            if (c + 1 < NCH2) {
                float4* dst = (c & 1) ? WB0 : WB1;
                #pragma unroll
                for (int i = 0; i < 4; i++) {
                    int t = tid + i * NT;
                    dst[(t >> 5) * 32 + (t & 31)] = pf[i];
                }
            }
            __syncthreads();
        }
    }

    // ---- BN2 + ReLU + W3 partial dots ----
    {
        #pragma unroll
        for (int p = 0; p < 4; p++) {
            float contrib = 0.f;
            #pragma unroll
            for (int cp = 0; cp < 2; cp++) {
                int c0 = 4*jq2 + 2*cp;
                float lo, hi; unpack2(acc2[p*2+cp], lo, hi);
                contrib += fmaxf(lo*S2f[c0]   + B2f[c0],   0.f) * W3s[c0];
                contrib += fmaxf(hi*S2f[c0+1] + B2f[c0+1], 0.f) * W3s[c0+1];
            }
            atomicAdd(&logit_s[4*rg2 + p], contrib);
        }
    }
    __syncthreads();

    // ---- Epilogue ----
    if (tid < ROWS) {
        float x = logit_s[tid] + fm_s[tid] + b3[0];
        out[b0 + tid] = 1.f / (1.f + expf(-x));
    }
}

extern "C" void kernel_launch(void* const* d_in, const int* in_sizes, int n_in,
                              void* d_out, int out_size)
{
    const int*   X    = (const int*)  d_in[0];
    const float* emb1 = (const float*)d_in[1];
    const float* emb2 = (const float*)d_in[2];
    const float* W1   = (const float*)d_in[3];
    const float* b1   = (const float*)d_in[4];
    const float* g1   = (const float*)d_in[5];
    const float* be1  = (const float*)d_in[6];
    const float* m1   = (const float*)d_in[7];
    const float* v1   = (const float*)d_in[8];
    const float* W2   = (const float*)d_in[9];
    const float* b2   = (const float*)d_in[10];
    const float* g2   = (const float*)d_in[11];
    const float* be2  = (const float*)d_in[12];
    const float* m2   = (const float*)d_in[13];
    const float* v2   = (const float*)d_in[14];
    const float* W3   = (const float*)d_in[15];
    const float* b3   = (const float*)d_in[16];
    float* out = (float*)d_out;

    int B = in_sizes[0] / NF;
    int V = in_sizes[1] / NF;

    int smem = SMEM_FLOATS * (int)sizeof(float);   // 176128 B
    cudaFuncSetAttribute(deepfm_v6, cudaFuncAttributeMaxDynamicSharedMemorySize, smem);
    deepfm_v6<<<B/ROWS, NT, smem>>>(X, emb1, emb2, W1, b1, g1, be1, m1, v1,
                                    W2, b2, g2, be2, m2, v2, W3, b3,
                                    out, B, V);
}